// round 2
// baseline (speedup 1.0000x reference)
#include <cuda_runtime.h>
#include <math.h>

#define NN 512
#define EE 512
#define MM 16384
#define FINW 64
#define HIDW 128
#define RTOT (EE*EE)   // 262144

// ---------------- scratch (device globals; no allocations allowed) ----------------
__device__ float g_efn[EE*FINW];
__device__ float g_cdiff[EE*3];
__device__ float g_T[(size_t)RTOT*96];        // [R,96]   100.7 MB
__device__ float g_m1T[(size_t)FINW*RTOT];    // [f][i*512+k] 64 MB
__device__ float g_m2T[(size_t)FINW*RTOT];    // [f][k*512+j] 64 MB
__device__ float g_mult[(size_t)FINW*RTOT];   // [f][i*512+j] 64 MB
__device__ float g_Tout[(size_t)RTOT*FINW];   // [R,64]   64 MB
__device__ float g_diag[EE*FINW];
__device__ float g_row[EE*FINW];
__device__ float g_col[EE*FINW];
__device__ float g_tot[FINW];
__device__ float g_tr[FINW];
__device__ float g_nbt1[EE*FINW];
__device__ float g_segx[NN*3];
__device__ float g_cnt[NN];
__device__ float g_nbt0[NN*FINW];

__device__ __forceinline__ float siluf(float v) {
    return v / (1.f + expf(-v));
}

// ---------------- 1. edge encoder + coord_diff ----------------
__global__ void k_edge(const float* __restrict__ h, const float* __restrict__ x,
                       const int* __restrict__ edges,
                       const float* __restrict__ ew1, const float* __restrict__ eb1,
                       const float* __restrict__ ew2, const float* __restrict__ eb2)
{
    __shared__ float hcat[128];
    __shared__ float hid[128];
    int e = blockIdx.x, t = threadIdx.x;
    int r = edges[e], c = edges[EE + e];
    if (t < 64) hcat[t] = h[r*64 + t];
    else        hcat[t] = h[c*64 + (t - 64)];
    if (t < 3)  g_cdiff[e*3 + t] = x[r*3 + t] - x[c*3 + t];
    __syncthreads();
    float acc = eb1[t];
#pragma unroll 8
    for (int k = 0; k < 128; k++) acc += hcat[k] * ew1[k*128 + t];
    hid[t] = siluf(acc);
    __syncthreads();
    if (t < 64) {
        float o = eb2[t];
#pragma unroll 8
        for (int k = 0; k < 128; k++) o += hid[k] * ew2[k*64 + t];
        g_efn[e*64 + t] = o;
    }
}

// ---------------- 2. VTV + positional encoding + scatter into dense T ----------------
__global__ void k_scatter(const int* __restrict__ nbe)
{
    int m = blockIdx.x, f = threadIdx.x;     // 128 threads, 96 active
    if (f >= 96) return;
    int a = nbe[m], b = nbe[MM + m];
    float val;
    if (f < 32) {
        float vtv = 0.f;
#pragma unroll
        for (int d = 0; d < 3; d++) vtv += g_cdiff[a*3 + d] * g_cdiff[b*3 + d];
        int i = f >> 1;
        // div_term = exp(log(1e4)*(2i/32));  ang = vtv*16/div_term
        float ang = vtv * 16.f * expf(-0.5756462732485115f * (float)i);
        val = (f & 1) ? cosf(ang) : sinf(ang);
    } else {
        val = g_efn[a*64 + (f - 32)] * g_efn[b*64 + (f - 32)];
    }
    atomicAdd(&g_T[((size_t)a*EE + b)*96 + f], val);
}

// ---------------- fused 2-layer MLP on a 64-row tile (K1 -> 128 -> 64) ----------------
// sA: [64 x K1] row-major, sBuf: 8192 floats, sHid: 8192 floats
template<int K1>
__device__ __forceinline__ void mlp_tile(const float* sA, float* sBuf, float* sHid,
    const float* __restrict__ W1, const float* __restrict__ b1,
    const float* __restrict__ W2, const float* __restrict__ b2,
    float acc2[4][4])
{
    int tid = threadIdx.x, ty = tid >> 4, tx = tid & 15;
    float acc[4][8];
#pragma unroll
    for (int i = 0; i < 4; i++)
#pragma unroll
        for (int u = 0; u < 8; u++) acc[i][u] = 0.f;

    for (int kc = 0; kc < K1; kc += 32) {
        for (int i = tid; i < 32*128; i += 256) sBuf[i] = W1[kc*128 + i];
        __syncthreads();
#pragma unroll
        for (int k = 0; k < 32; k++) {
            float a[4];
#pragma unroll
            for (int i = 0; i < 4; i++) a[i] = sA[(ty*4 + i)*K1 + kc + k];
            float4 b0 = *(const float4*)&sBuf[k*128 + tx*8];
            float4 b1v = *(const float4*)&sBuf[k*128 + tx*8 + 4];
#pragma unroll
            for (int i = 0; i < 4; i++) {
                float av = a[i];
                acc[i][0] += av * b0.x;  acc[i][1] += av * b0.y;
                acc[i][2] += av * b0.z;  acc[i][3] += av * b0.w;
                acc[i][4] += av * b1v.x; acc[i][5] += av * b1v.y;
                acc[i][6] += av * b1v.z; acc[i][7] += av * b1v.w;
            }
        }
        __syncthreads();
    }
    // hidden with bias + SiLU
#pragma unroll
    for (int i = 0; i < 4; i++)
#pragma unroll
        for (int u = 0; u < 8; u++) {
            int j = tx*8 + u;
            float v = acc[i][u] + b1[j];
            sHid[(ty*4 + i)*128 + j] = siluf(v);
        }
    // load W2 (128x64) into sBuf
    for (int i = tid; i < 128*64; i += 256) sBuf[i] = W2[i];
    __syncthreads();
#pragma unroll
    for (int i = 0; i < 4; i++)
#pragma unroll
        for (int u = 0; u < 4; u++) acc2[i][u] = 0.f;
#pragma unroll 4
    for (int k = 0; k < 128; k++) {
        float a[4];
#pragma unroll
        for (int i = 0; i < 4; i++) a[i] = sHid[(ty*4 + i)*128 + k];
        float4 b = *(const float4*)&sBuf[k*64 + tx*4];
#pragma unroll
        for (int i = 0; i < 4; i++) {
            float av = a[i];
            acc2[i][0] += av * b.x; acc2[i][1] += av * b.y;
            acc2[i][2] += av * b.z; acc2[i][3] += av * b.w;
        }
    }
#pragma unroll
    for (int i = 0; i < 4; i++)
#pragma unroll
        for (int u = 0; u < 4; u++) acc2[i][u] += b2[tx*4 + u];
    __syncthreads();
}

// ---------------- 3. m1/m2 MLPs, write transposed [f][row] ----------------
__global__ void __launch_bounds__(256) k_mlp12(
    const float* __restrict__ p1w1, const float* __restrict__ p1b1,
    const float* __restrict__ p1w2, const float* __restrict__ p1b2,
    const float* __restrict__ p2w1, const float* __restrict__ p2b1,
    const float* __restrict__ p2w2, const float* __restrict__ p2b2)
{
    extern __shared__ float smem[];
    float* sA   = smem;            // 64*96 = 6144
    float* sBuf = sA + 64*96;      // 8192
    float* sHid = sBuf + 8192;     // 8192
    int base = blockIdx.x * 64;
    int tid = threadIdx.x, ty = tid >> 4, tx = tid & 15;

    const float* Tp = &g_T[(size_t)base * 96];
    for (int i = tid; i < 64*96; i += 256) sA[i] = Tp[i];  // fully contiguous
    __syncthreads();

    float acc2[4][4];
    mlp_tile<96>(sA, sBuf, sHid, p1w1, p1b1, p1w2, p1b2, acc2);
#pragma unroll
    for (int i = 0; i < 4; i++)
#pragma unroll
        for (int u = 0; u < 4; u++) sHid[(tx*4 + u)*64 + ty*4 + i] = acc2[i][u];
    __syncthreads();
    for (int i = tid; i < 4096; i += 256) {
        int f = i >> 6, r = i & 63;
        g_m1T[(size_t)f*RTOT + base + r] = sHid[i];
    }

    mlp_tile<96>(sA, sBuf, sHid, p2w1, p2b1, p2w2, p2b2, acc2);
#pragma unroll
    for (int i = 0; i < 4; i++)
#pragma unroll
        for (int u = 0; u < 4; u++) sHid[(tx*4 + u)*64 + ty*4 + i] = acc2[i][u];
    __syncthreads();
    for (int i = tid; i < 4096; i += 256) {
        int f = i >> 6, r = i & 63;
        g_m2T[(size_t)f*RTOT + base + r] = sHid[i];
    }
}

// ---------------- 4. batched 512x512x512 GEMM per feature ----------------
__global__ void __launch_bounds__(256) k_bat()
{
    __shared__ float Ast[16*64];
    __shared__ float Bs[16*64];
    int f = blockIdx.z, bi = blockIdx.y, bj = blockIdx.x;
    const float* A = &g_m1T[(size_t)f*RTOT];
    const float* B = &g_m2T[(size_t)f*RTOT];
    int tid = threadIdx.x, ty = tid >> 4, tx = tid & 15;
    float acc[4][4];
#pragma unroll
    for (int i = 0; i < 4; i++)
#pragma unroll
        for (int u = 0; u < 4; u++) acc[i][u] = 0.f;

    int ra = tid >> 2;        // 0..63
    int ka = (tid & 3) * 4;   // 0,4,8,12
    int kb = tid >> 4;        // 0..15
    int cb = (tid & 15) * 4;  // 0..60

    for (int kc = 0; kc < 512; kc += 16) {
        float4 av = *(const float4*)&A[(size_t)(bi*64 + ra)*512 + kc + ka];
        Ast[(ka + 0)*64 + ra] = av.x;
        Ast[(ka + 1)*64 + ra] = av.y;
        Ast[(ka + 2)*64 + ra] = av.z;
        Ast[(ka + 3)*64 + ra] = av.w;
        *(float4*)&Bs[kb*64 + cb] = *(const float4*)&B[(size_t)(kc + kb)*512 + bj*64 + cb];
        __syncthreads();
#pragma unroll
        for (int k = 0; k < 16; k++) {
            float4 a = *(const float4*)&Ast[k*64 + ty*4];
            float4 b = *(const float4*)&Bs[k*64 + tx*4];
            acc[0][0] += a.x*b.x; acc[0][1] += a.x*b.y; acc[0][2] += a.x*b.z; acc[0][3] += a.x*b.w;
            acc[1][0] += a.y*b.x; acc[1][1] += a.y*b.y; acc[1][2] += a.y*b.z; acc[1][3] += a.y*b.w;
            acc[2][0] += a.z*b.x; acc[2][1] += a.z*b.y; acc[2][2] += a.z*b.z; acc[2][3] += a.z*b.w;
            acc[3][0] += a.w*b.x; acc[3][1] += a.w*b.y; acc[3][2] += a.w*b.z; acc[3][3] += a.w*b.w;
        }
        __syncthreads();
    }
    float* C = &g_mult[(size_t)f*RTOT];
#pragma unroll
    for (int i = 0; i < 4; i++) {
        float4 v = make_float4(acc[i][0], acc[i][1], acc[i][2], acc[i][3]);
        *(float4*)&C[(size_t)(bi*64 + ty*4 + i)*512 + bj*64 + tx*4] = v;
    }
}

// ---------------- 5. output MLP on concat(T, mult) ----------------
__global__ void __launch_bounds__(256) k_mlp3(
    const float* __restrict__ w1, const float* __restrict__ b1,
    const float* __restrict__ w2, const float* __restrict__ b2)
{
    extern __shared__ float smem[];
    float* sA   = smem;             // 64*160 = 10240
    float* sBuf = sA + 64*160;      // 8192
    float* sHid = sBuf + 8192;      // 8192
    int base = blockIdx.x * 64;
    int tid = threadIdx.x, ty = tid >> 4, tx = tid & 15;

    const float* Tp = &g_T[(size_t)base * 96];
    for (int i = tid; i < 64*96; i += 256) {
        int r = i / 96, k = i % 96;
        sA[r*160 + k] = Tp[i];
    }
    for (int i = tid; i < 64*64; i += 256) {
        int f = i >> 6, r = i & 63;
        sA[r*160 + 96 + f] = g_mult[(size_t)f*RTOT + base + r];
    }
    __syncthreads();

    float acc2[4][4];
    mlp_tile<160>(sA, sBuf, sHid, w1, b1, w2, b2, acc2);
#pragma unroll
    for (int i = 0; i < 4; i++) {
        float4 v = make_float4(acc2[i][0], acc2[i][1], acc2[i][2], acc2[i][3]);
        *(float4*)&g_Tout[(size_t)(base + ty*4 + i)*64 + tx*4] = v;
    }
}

// ---------------- 6. IGN reductions ----------------
__global__ void k_rowred()
{
    int i = blockIdx.x, f = threadIdx.x;   // 64 threads
    float rs = 0.f;
#pragma unroll 8
    for (int j = 0; j < 512; j++) rs += g_Tout[((size_t)i*512 + j)*64 + f];
    float dg = g_Tout[((size_t)i*512 + i)*64 + f];
    g_row[i*64 + f] = rs;
    g_diag[i*64 + f] = dg;
    atomicAdd(&g_tot[f], rs);
    atomicAdd(&g_tr[f], dg);
}

__global__ void k_colred()
{
    int j = blockIdx.x, f = threadIdx.x;
    float cs = 0.f;
#pragma unroll 8
    for (int i = 0; i < 512; i++) cs += g_Tout[((size_t)i*512 + j)*64 + f];
    g_col[j*64 + f] = cs;
}

__global__ void k_nbt1(const float* __restrict__ ign_w, const float* __restrict__ ign_b)
{
    __shared__ float feat[320];
    int e = blockIdx.x, t = threadIdx.x;   // 64 threads
    feat[t]       = g_diag[e*64 + t];
    feat[64 + t]  = g_row[e*64 + t];
    feat[128 + t] = g_col[e*64 + t];
    feat[192 + t] = g_tot[t];
    feat[256 + t] = g_tr[t];
    __syncthreads();
    float o = ign_b[t];
#pragma unroll 8
    for (int k = 0; k < 320; k++) o += feat[k] * ign_w[k*64 + t];
    g_nbt1[e*64 + t] = o;
}

// ---------------- 7. coord weights + segment scatter ----------------
__global__ void k_coord(const int* __restrict__ edges,
                        const float* __restrict__ cw1, const float* __restrict__ cb1,
                        const float* __restrict__ cw2)
{
    __shared__ float nb[64];
    __shared__ float red[128];
    int e = blockIdx.x, t = threadIdx.x;   // 128 threads
    if (t < 64) nb[t] = g_nbt1[e*64 + t];
    __syncthreads();
    float acc = cb1[t];
#pragma unroll 8
    for (int k = 0; k < 64; k++) acc += nb[k] * cw1[k*128 + t];
    red[t] = siluf(acc) * cw2[t];
    __syncthreads();
    for (int st = 64; st > 0; st >>= 1) {
        if (t < st) red[t] += red[t + st];
        __syncthreads();
    }
    float w = red[0];
    int r = edges[e];
    if (t < 3)  atomicAdd(&g_segx[r*3 + t], g_cdiff[e*3 + t] * w);
    if (t == 3) atomicAdd(&g_cnt[r], 1.f);
    if (t >= 64) atomicAdd(&g_nbt0[r*64 + (t - 64)], nb[t - 64]);
}

// ---------------- 8. node update + coord finalize ----------------
__global__ void k_node(const float* __restrict__ h, const float* __restrict__ x,
                       const float* __restrict__ nw1, const float* __restrict__ nb1,
                       const float* __restrict__ nw2, const float* __restrict__ nb2,
                       float* __restrict__ out)
{
    __shared__ float a[64];
    __shared__ float hid[128];
    int n = blockIdx.x, t = threadIdx.x;   // 128 threads
    if (t < 64) a[t] = g_nbt0[n*64 + t];
    __syncthreads();
    float acc = nb1[t];
#pragma unroll 8
    for (int k = 0; k < 64; k++) acc += a[k] * nw1[k*128 + t];
    hid[t] = siluf(acc);
    __syncthreads();
    if (t < 64) {
        float o = nb2[t];
#pragma unroll 8
        for (int k = 0; k < 128; k++) o += hid[k] * nw2[k*64 + t];
        out[n*64 + t] = h[n*64 + t] + o;
    } else if (t < 67) {
        int d = t - 64;
        float c = g_cnt[n];
        if (c < 1.f) c = 1.f;
        out[NN*64 + n*3 + d] = x[n*3 + d] + g_segx[n*3 + d] / c;
    }
}

__global__ void k_copy_ea(const float* __restrict__ ea, float* __restrict__ out)
{
    int i = blockIdx.x * blockDim.x + threadIdx.x;
    if (i < EE*4) out[NN*64 + NN*3 + i] = ea[i];
}

// ---------------- host ----------------
extern "C" void kernel_launch(void* const* d_in, const int* in_sizes, int n_in,
                              void* d_out, int out_size)
{
    const float* h     = (const float*)d_in[0];
    const float* x     = (const float*)d_in[1];
    const int*   edges = (const int*)d_in[2];
    const int*   nbe   = (const int*)d_in[3];
    const float* ea    = (const float*)d_in[4];
    int wb = n_in - 25;   // robust to nb_num_nodes occupying a slot or not
    const float* ew1  = (const float*)d_in[wb + 0];
    const float* eb1  = (const float*)d_in[wb + 1];
    const float* ew2  = (const float*)d_in[wb + 2];
    const float* eb2  = (const float*)d_in[wb + 3];
    const float* p1w1 = (const float*)d_in[wb + 4];
    const float* p1b1 = (const float*)d_in[wb + 5];
    const float* p1w2 = (const float*)d_in[wb + 6];
    const float* p1b2 = (const float*)d_in[wb + 7];
    const float* p2w1 = (const float*)d_in[wb + 8];
    const float* p2b1 = (const float*)d_in[wb + 9];
    const float* p2w2 = (const float*)d_in[wb + 10];
    const float* p2b2 = (const float*)d_in[wb + 11];
    const float* p3w1 = (const float*)d_in[wb + 12];
    const float* p3b1 = (const float*)d_in[wb + 13];
    const float* p3w2 = (const float*)d_in[wb + 14];
    const float* p3b2 = (const float*)d_in[wb + 15];
    const float* ignw = (const float*)d_in[wb + 16];
    const float* ignb = (const float*)d_in[wb + 17];
    const float* cw1  = (const float*)d_in[wb + 18];
    const float* cb1  = (const float*)d_in[wb + 19];
    const float* cw2  = (const float*)d_in[wb + 20];
    const float* ndw1 = (const float*)d_in[wb + 21];
    const float* ndb1 = (const float*)d_in[wb + 22];
    const float* ndw2 = (const float*)d_in[wb + 23];
    const float* ndb2 = (const float*)d_in[wb + 24];
    float* out = (float*)d_out;

    cudaFuncSetAttribute(k_mlp12, cudaFuncAttributeMaxDynamicSharedMemorySize, (64*96 + 8192 + 8192) * 4);
    cudaFuncSetAttribute(k_mlp3,  cudaFuncAttributeMaxDynamicSharedMemorySize, (64*160 + 8192 + 8192) * 4);

    void* p;
    cudaGetSymbolAddress(&p, g_T);    cudaMemsetAsync(p, 0, sizeof(float)*(size_t)RTOT*96, 0);
    cudaGetSymbolAddress(&p, g_segx); cudaMemsetAsync(p, 0, sizeof(float)*NN*3, 0);
    cudaGetSymbolAddress(&p, g_cnt);  cudaMemsetAsync(p, 0, sizeof(float)*NN, 0);
    cudaGetSymbolAddress(&p, g_nbt0); cudaMemsetAsync(p, 0, sizeof(float)*NN*FINW, 0);
    cudaGetSymbolAddress(&p, g_tot);  cudaMemsetAsync(p, 0, sizeof(float)*FINW, 0);
    cudaGetSymbolAddress(&p, g_tr);   cudaMemsetAsync(p, 0, sizeof(float)*FINW, 0);

    k_edge<<<EE, 128>>>(h, x, edges, ew1, eb1, ew2, eb2);
    k_scatter<<<MM, 128>>>(nbe);
    k_mlp12<<<RTOT/64, 256, (64*96 + 8192 + 8192) * 4>>>(p1w1, p1b1, p1w2, p1b2,
                                                         p2w1, p2b1, p2w2, p2b2);
    k_bat<<<dim3(8, 8, 64), 256>>>();
    k_mlp3<<<RTOT/64, 256, (64*160 + 8192 + 8192) * 4>>>(p3w1, p3b1, p3w2, p3b2);
    k_rowred<<<EE, 64>>>();
    k_colred<<<EE, 64>>>();
    k_nbt1<<<EE, 64>>>(ignw, ignb);
    k_coord<<<EE, 128>>>(edges, cw1, cb1, cw2);
    k_node<<<NN, 128>>>(h, x, ndw1, ndb1, ndw2, ndb2, out);
    k_copy_ea<<<8, 256>>>(ea, out);
}

// round 3
// speedup vs baseline: 3.0437x; 3.0437x over previous
#include <cuda_runtime.h>
#include <math.h>

#define NN 512
#define EE 512
#define MM 16384
#define FINW 64
#define RTOT (EE*EE)   // 262144
#define SMAX 16384

// ---------------- scratch (device globals) ----------------
__device__ float g_efn[EE*FINW];
__device__ float g_cdiff[EE*3];
__device__ int   g_map[RTOT];          // 0 = empty, then flag/slot
__device__ int   g_cells[SMAX];
__device__ int   g_nnz;
__device__ float g_Tval[(size_t)SMAX*96];
__device__ float g_S1[(size_t)SMAX*64];
__device__ float g_S2[(size_t)SMAX*64];
__device__ float g_rowS1[EE*64];
__device__ float g_colS2[EE*64];
__device__ float g_c1[64], g_c2[64], g_u0[128];
__device__ float g_atab[EE*128], g_btab[EE*128];
__device__ int   g_cntA[EE], g_cntB[EE], g_offA[EE], g_offB[EE], g_curA[EE], g_curB[EE];
__device__ int   g_listA[SMAX], g_listB[SMAX];
__device__ float g_SS[(size_t)RTOT*64];    // 64 MB
__device__ float g_Z[(size_t)RTOT*128];    // 128 MB
__device__ float g_Hrow[EE*128], g_Hcol[EE*128], g_Hdiag[EE*128];
__device__ float g_diag[EE*FINW], g_row[EE*FINW], g_col[EE*FINW];
__device__ float g_tot[FINW], g_tr[FINW];
__device__ float g_nbt1[EE*FINW];
__device__ float g_segx[NN*3];
__device__ float g_cnt[NN];
__device__ float g_nbt0[NN*FINW];

__device__ __forceinline__ float siluf(float v) {
    return v * __fdividef(1.f, 1.f + __expf(-v));
}

// ---------------- 1. edge encoder + coord_diff ----------------
__global__ void k_edge(const float* __restrict__ h, const float* __restrict__ x,
                       const int* __restrict__ edges,
                       const float* __restrict__ ew1, const float* __restrict__ eb1,
                       const float* __restrict__ ew2, const float* __restrict__ eb2)
{
    __shared__ float hcat[128];
    __shared__ float hid[128];
    int e = blockIdx.x, t = threadIdx.x;
    int r = edges[e], c = edges[EE + e];
    if (t < 64) hcat[t] = h[r*64 + t];
    else        hcat[t] = h[c*64 + (t - 64)];
    if (t < 3)  g_cdiff[e*3 + t] = x[r*3 + t] - x[c*3 + t];
    __syncthreads();
    float acc = eb1[t];
#pragma unroll 8
    for (int k = 0; k < 128; k++) acc += hcat[k] * ew1[k*128 + t];
    hid[t] = siluf(acc);
    __syncthreads();
    if (t < 64) {
        float o = eb2[t];
#pragma unroll 8
        for (int k = 0; k < 128; k++) o += hid[k] * ew2[k*64 + t];
        g_efn[e*64 + t] = o;
    }
}

// ---------------- 2. occupancy flag + compaction ----------------
__global__ void k_flag(const int* __restrict__ nbe)
{
    int m = blockIdx.x * blockDim.x + threadIdx.x;
    if (m < MM) g_map[nbe[m]*EE + nbe[MM + m]] = 1;
}

__global__ void k_compact()
{
    int cell = blockIdx.x * blockDim.x + threadIdx.x;
    if (cell < RTOT && g_map[cell] == 1) {
        int slot = atomicAdd(&g_nnz, 1);
        g_map[cell] = slot;
        g_cells[slot] = cell;
    }
}

// ---------------- 3. VTV + PE + scatter into compact T ----------------
__global__ void k_scat(const int* __restrict__ nbe)
{
    int m = blockIdx.x, f = threadIdx.x;  // 128 threads, 96 active
    if (f >= 96) return;
    int a = nbe[m], b = nbe[MM + m];
    float val;
    if (f < 32) {
        float vtv = 0.f;
#pragma unroll
        for (int d = 0; d < 3; d++) vtv += g_cdiff[a*3 + d] * g_cdiff[b*3 + d];
        int i = f >> 1;
        float ang = vtv * 16.f * expf(-0.5756462732485115f * (float)i);
        val = (f & 1) ? cosf(ang) : sinf(ang);
    } else {
        val = g_efn[a*64 + (f - 32)] * g_efn[b*64 + (f - 32)];
    }
    int slot = g_map[a*EE + b];
    atomicAdd(&g_Tval[(size_t)slot*96 + f], val);
}

// ---------------- 4. constants c1,c2,u0 ----------------
__global__ void k_const(const float* __restrict__ p1b1, const float* __restrict__ p1w2, const float* __restrict__ p1b2,
                        const float* __restrict__ p2b1, const float* __restrict__ p2w2, const float* __restrict__ p2b2,
                        const float* __restrict__ p3w1, const float* __restrict__ p3b1)
{
    __shared__ float h1[128], h2[128], cc[64];
    int t = threadIdx.x;  // 128
    h1[t] = siluf(p1b1[t]);
    h2[t] = siluf(p2b1[t]);
    __syncthreads();
    if (t < 64) {
        float a = p1b2[t], b = p2b2[t];
#pragma unroll 8
        for (int k = 0; k < 128; k++) { a += h1[k]*p1w2[k*64+t]; b += h2[k]*p2w2[k*64+t]; }
        g_c1[t] = a; g_c2[t] = b; cc[t] = a*b;
    }
    __syncthreads();
    float u = p3b1[t];
#pragma unroll 8
    for (int f = 0; f < 64; f++) u += 512.f * cc[f] * p3w1[(96+f)*128 + t];
    g_u0[t] = u;
}

// ---------------- fused 2-layer MLP on 64-row tile (K1 -> 128 -> 64) ----------------
template<int K1>
__device__ __forceinline__ void mlp_tile(const float* sA, float* sBuf, float* sHid,
    const float* __restrict__ W1, const float* __restrict__ b1,
    const float* __restrict__ W2, const float* __restrict__ b2,
    float acc2[4][4])
{
    int tid = threadIdx.x, ty = tid >> 4, tx = tid & 15;
    float acc[4][8];
#pragma unroll
    for (int i = 0; i < 4; i++)
#pragma unroll
        for (int u = 0; u < 8; u++) acc[i][u] = 0.f;

    for (int kc = 0; kc < K1; kc += 32) {
        for (int i = tid; i < 32*128; i += 256) sBuf[i] = W1[kc*128 + i];
        __syncthreads();
#pragma unroll
        for (int k = 0; k < 32; k++) {
            float a[4];
#pragma unroll
            for (int i = 0; i < 4; i++) a[i] = sA[(ty*4 + i)*K1 + kc + k];
            float4 b0 = *(const float4*)&sBuf[k*128 + tx*8];
            float4 b1v = *(const float4*)&sBuf[k*128 + tx*8 + 4];
#pragma unroll
            for (int i = 0; i < 4; i++) {
                float av = a[i];
                acc[i][0] += av * b0.x;  acc[i][1] += av * b0.y;
                acc[i][2] += av * b0.z;  acc[i][3] += av * b0.w;
                acc[i][4] += av * b1v.x; acc[i][5] += av * b1v.y;
                acc[i][6] += av * b1v.z; acc[i][7] += av * b1v.w;
            }
        }
        __syncthreads();
    }
#pragma unroll
    for (int i = 0; i < 4; i++)
#pragma unroll
        for (int u = 0; u < 8; u++) {
            int j = tx*8 + u;
            sHid[(ty*4 + i)*128 + j] = siluf(acc[i][u] + b1[j]);
        }
    for (int i = tid; i < 128*64; i += 256) sBuf[i] = W2[i];
    __syncthreads();
#pragma unroll
    for (int i = 0; i < 4; i++)
#pragma unroll
        for (int u = 0; u < 4; u++) acc2[i][u] = 0.f;
#pragma unroll 4
    for (int k = 0; k < 128; k++) {
        float a[4];
#pragma unroll
        for (int i = 0; i < 4; i++) a[i] = sHid[(ty*4 + i)*128 + k];
        float4 b = *(const float4*)&sBuf[k*64 + tx*4];
#pragma unroll
        for (int i = 0; i < 4; i++) {
            float av = a[i];
            acc2[i][0] += av * b.x; acc2[i][1] += av * b.y;
            acc2[i][2] += av * b.z; acc2[i][3] += av * b.w;
        }
    }
#pragma unroll
    for (int i = 0; i < 4; i++)
#pragma unroll
        for (int u = 0; u < 4; u++) acc2[i][u] += b2[tx*4 + u];
    __syncthreads();
}

// ---------------- 5. sparse MLPs: S1,S2 + row/col sums ----------------
__global__ void __launch_bounds__(256) k_smlp(
    const float* __restrict__ p1w1, const float* __restrict__ p1b1,
    const float* __restrict__ p1w2, const float* __restrict__ p1b2,
    const float* __restrict__ p2w1, const float* __restrict__ p2b1,
    const float* __restrict__ p2w2, const float* __restrict__ p2b2)
{
    extern __shared__ float smem[];
    float* sA   = smem;            // 64*96
    float* sBuf = sA + 64*96;
    float* sHid = sBuf + 8192;
    int base = blockIdx.x * 64;
    int tid = threadIdx.x, ty = tid >> 4, tx = tid & 15;
    int nnz = g_nnz;

    const float* Tp = &g_Tval[(size_t)base * 96];
    for (int i = tid; i < 64*96; i += 256) sA[i] = Tp[i];
    __syncthreads();

    float acc2[4][4];
    mlp_tile<96>(sA, sBuf, sHid, p1w1, p1b1, p1w2, p1b2, acc2);
#pragma unroll
    for (int i = 0; i < 4; i++) {
        int slot = base + ty*4 + i;
        if (slot < nnz) {
            int cell = g_cells[slot];
#pragma unroll
            for (int u = 0; u < 4; u++) {
                int f = tx*4 + u;
                float v = acc2[i][u] - g_c1[f];
                g_S1[(size_t)slot*64 + f] = v;
                atomicAdd(&g_rowS1[(cell >> 9)*64 + f], v);
            }
        }
    }

    mlp_tile<96>(sA, sBuf, sHid, p2w1, p2b1, p2w2, p2b2, acc2);
#pragma unroll
    for (int i = 0; i < 4; i++) {
        int slot = base + ty*4 + i;
        if (slot < nnz) {
            int cell = g_cells[slot];
#pragma unroll
            for (int u = 0; u < 4; u++) {
                int f = tx*4 + u;
                float v = acc2[i][u] - g_c2[f];
                g_S2[(size_t)slot*64 + f] = v;
                atomicAdd(&g_colS2[(cell & 511)*64 + f], v);
            }
        }
    }
}

// ---------------- 6. a_i / b_j tables ----------------
__global__ void k_ab(const float* __restrict__ p3w1)
{
    __shared__ float r[64];
    int b = blockIdx.x, t = threadIdx.x;  // 128
    if (b < 512) {
        int i = b;
        if (t < 64) r[t] = g_rowS1[i*64 + t] * g_c2[t];
        __syncthreads();
        float a = 0.f;
#pragma unroll 8
        for (int f = 0; f < 64; f++) a += r[f] * p3w1[(96+f)*128 + t];
        g_atab[i*128 + t] = a;
    } else {
        int j = b - 512;
        if (t < 64) r[t] = g_colS2[j*64 + t] * g_c1[t];
        __syncthreads();
        float a = 0.f;
#pragma unroll 8
        for (int f = 0; f < 64; f++) a += r[f] * p3w1[(96+f)*128 + t];
        g_btab[j*128 + t] = a;
    }
}

// ---------------- 7. group slots by middle index ----------------
__global__ void k_cnt()
{
    int s = blockIdx.x * blockDim.x + threadIdx.x;
    if (s < g_nnz) {
        int cell = g_cells[s];
        atomicAdd(&g_cntA[cell & 511], 1);   // S1 entries grouped by k = col
        atomicAdd(&g_cntB[cell >> 9], 1);    // S2 entries grouped by k = row
    }
}

__global__ void k_scan()
{
    __shared__ int s[512];
    int t = threadIdx.x;  // 512
    // scan A
    s[t] = g_cntA[t]; __syncthreads();
    for (int d = 1; d < 512; d <<= 1) {
        int v = (t >= d) ? s[t - d] : 0;
        __syncthreads();
        s[t] += v;
        __syncthreads();
    }
    int exc = s[t] - g_cntA[t];
    g_offA[t] = exc; g_curA[t] = exc;
    __syncthreads();
    // scan B
    s[t] = g_cntB[t]; __syncthreads();
    for (int d = 1; d < 512; d <<= 1) {
        int v = (t >= d) ? s[t - d] : 0;
        __syncthreads();
        s[t] += v;
        __syncthreads();
    }
    exc = s[t] - g_cntB[t];
    g_offB[t] = exc; g_curB[t] = exc;
}

__global__ void k_fill()
{
    int s = blockIdx.x * blockDim.x + threadIdx.x;
    if (s < g_nnz) {
        int cell = g_cells[s];
        int pa = atomicAdd(&g_curA[cell & 511], 1);
        g_listA[pa] = s;
        int pb = atomicAdd(&g_curB[cell >> 9], 1);
        g_listB[pb] = s;
    }
}

// ---------------- 8. sparse-sparse product: SS[i,j,f] += S1[i,k,f]*S2[k,j,f] ----------------
__global__ void __launch_bounds__(256) k_ss()
{
    __shared__ float sA[64*64];
    __shared__ float sB[64*64];
    __shared__ int ri[64], cj[64];
    int k = blockIdx.x, tid = threadIdx.x;
    int cA = g_cntA[k], cB = g_cntB[k];
    if (cA == 0 || cB == 0) return;
    int oA = g_offA[k], oB = g_offB[k];

    for (int a0 = 0; a0 < cA; a0 += 64) {
        int nA = min(64, cA - a0);
        __syncthreads();
        for (int x = tid; x < nA*64; x += 256) {
            int r = x >> 6;
            int slot = g_listA[oA + a0 + r];
            sA[x] = g_S1[(size_t)slot*64 + (x & 63)];
        }
        for (int r = tid; r < nA; r += 256) ri[r] = g_cells[g_listA[oA + a0 + r]] >> 9;
        for (int b0 = 0; b0 < cB; b0 += 64) {
            int nB = min(64, cB - b0);
            __syncthreads();
            for (int x = tid; x < nB*64; x += 256) {
                int c = x >> 6;
                int slot = g_listB[oB + b0 + c];
                sB[x] = g_S2[(size_t)slot*64 + (x & 63)];
            }
            for (int c = tid; c < nB; c += 256) cj[c] = g_cells[g_listB[oB + b0 + c]] & 511;
            __syncthreads();
            int f = tid & 63, pc = tid >> 6;  // 4 columns in flight
            for (int r = 0; r < nA; r++) {
                float av = sA[r*64 + f];
                int ibase = ri[r];
                for (int c = pc; c < nB; c += 4) {
                    atomicAdd(&g_SS[((size_t)ibase*512 + cj[c])*64 + f], av * sB[c*64 + f]);
                }
            }
        }
    }
}

// ---------------- 9. Z = SS @ W1m  (262144 x 64 @ 64 x 128) ----------------
__global__ void __launch_bounds__(256) k_zgemm(const float* __restrict__ p3w1)
{
    extern __shared__ float dsm[];
    float* sA = dsm;             // [64 cells][68]
    float* sB = dsm + 64*68;     // [64 k][128]
    size_t base = (size_t)blockIdx.x * 64;
    int tid = threadIdx.x;

    for (int x = tid*4; x < 4096; x += 1024) {
        float4 v = *(const float4*)&g_SS[base*64 + x];
        int cell = x >> 6, k = x & 63;
        *(float4*)&sA[cell*68 + k] = v;
    }
    for (int x = tid*4; x < 8192; x += 1024) {
        int k = x >> 7, n = x & 127;
        *(float4*)&sB[x] = *(const float4*)&p3w1[(96 + k)*128 + n];
    }
    __syncthreads();

    int ty = tid >> 4, tx = tid & 15;
    float acc[4][8];
#pragma unroll
    for (int i = 0; i < 4; i++)
#pragma unroll
        for (int u = 0; u < 8; u++) acc[i][u] = 0.f;

#pragma unroll 16
    for (int k = 0; k < 64; k++) {
        float a[4];
#pragma unroll
        for (int i = 0; i < 4; i++) a[i] = sA[(ty*4 + i)*68 + k];
        float4 b0 = *(const float4*)&sB[k*128 + tx*8];
        float4 b1 = *(const float4*)&sB[k*128 + tx*8 + 4];
#pragma unroll
        for (int i = 0; i < 4; i++) {
            float av = a[i];
            acc[i][0] += av * b0.x; acc[i][1] += av * b0.y;
            acc[i][2] += av * b0.z; acc[i][3] += av * b0.w;
            acc[i][4] += av * b1.x; acc[i][5] += av * b1.y;
            acc[i][6] += av * b1.z; acc[i][7] += av * b1.w;
        }
    }
#pragma unroll
    for (int i = 0; i < 4; i++) {
        size_t row = base + ty*4 + i;
        *(float4*)&g_Z[row*128 + tx*8]     = make_float4(acc[i][0], acc[i][1], acc[i][2], acc[i][3]);
        *(float4*)&g_Z[row*128 + tx*8 + 4] = make_float4(acc[i][4], acc[i][5], acc[i][6], acc[i][7]);
    }
}

// ---------------- 10. add sparse T contribution: Z[cell] += W1t^T Tval ----------------
__global__ void k_tc(const float* __restrict__ p3w1)
{
    __shared__ float tv[96];
    int slot = blockIdx.x, t = threadIdx.x;  // 128
    if (slot >= g_nnz) return;
    if (t < 96) tv[t] = g_Tval[(size_t)slot*96 + t];
    __syncthreads();
    float acc = 0.f;
#pragma unroll 8
    for (int k = 0; k < 96; k++) acc += tv[k] * p3w1[k*128 + t];
    size_t cell = (size_t)g_cells[slot];
    g_Z[cell*128 + t] += acc;
}

// ---------------- 11. silu + reductions of hid ----------------
__global__ void k_hrow()
{
    int i = blockIdx.x, t = threadIdx.x;  // 128
    float addi = g_u0[t] + g_atab[i*128 + t];
    const float* zrow = &g_Z[(size_t)i*512*128];
    float rs = 0.f;
    for (int j = 0; j < 512; j++) {
        float z = zrow[j*128 + t] + addi + g_btab[j*128 + t];
        float hv = siluf(z);
        rs += hv;
        if (j == i) g_Hdiag[i*128 + t] = hv;
    }
    g_Hrow[i*128 + t] = rs;
}

__global__ void k_hcol()
{
    int j = blockIdx.x, t = threadIdx.x;  // 128
    float addj = g_u0[t] + g_btab[j*128 + t];
    float cs = 0.f;
    for (int i = 0; i < 512; i++) {
        float z = g_Z[((size_t)i*512 + j)*128 + t] + addj + g_atab[i*128 + t];
        cs += siluf(z);
    }
    g_Hcol[j*128 + t] = cs;
}

// ---------------- 12. apply W2 to aggregates ----------------
__global__ void k_ign(const float* __restrict__ w2, const float* __restrict__ b2)
{
    __shared__ float hd[128], hr[128], hc[128];
    int e = blockIdx.x, t = threadIdx.x;  // 128 threads, 513 blocks
    if (e < 512) {
        hd[t] = g_Hdiag[e*128 + t];
        hr[t] = g_Hrow[e*128 + t];
        hc[t] = g_Hcol[e*128 + t];
        __syncthreads();
        if (t < 64) {
            float d = 0.f, r = 0.f, c = 0.f;
#pragma unroll 8
            for (int k = 0; k < 128; k++) {
                float w = w2[k*64 + t];
                d += hd[k]*w; r += hr[k]*w; c += hc[k]*w;
            }
            float bb = b2[t];
            g_diag[e*64 + t] = d + bb;
            g_row[e*64 + t]  = r + 512.f*bb;
            g_col[e*64 + t]  = c + 512.f*bb;
        }
    } else {
        float st = 0.f, sr = 0.f;
        for (int i = 0; i < 512; i++) { st += g_Hrow[i*128 + t]; sr += g_Hdiag[i*128 + t]; }
        hd[t] = st; hr[t] = sr;
        __syncthreads();
        if (t < 64) {
            float a = 0.f, b = 0.f;
#pragma unroll 8
            for (int k = 0; k < 128; k++) { float w = w2[k*64 + t]; a += hd[k]*w; b += hr[k]*w; }
            g_tot[t] = a + 262144.f*b2[t];
            g_tr[t]  = b + 512.f*b2[t];
        }
    }
}

// ---------------- 13. IGN linear ----------------
__global__ void k_nbt1(const float* __restrict__ ign_w, const float* __restrict__ ign_b)
{
    __shared__ float feat[320];
    int e = blockIdx.x, t = threadIdx.x;   // 64
    feat[t]       = g_diag[e*64 + t];
    feat[64 + t]  = g_row[e*64 + t];
    feat[128 + t] = g_col[e*64 + t];
    feat[192 + t] = g_tot[t];
    feat[256 + t] = g_tr[t];
    __syncthreads();
    float o = ign_b[t];
#pragma unroll 8
    for (int k = 0; k < 320; k++) o += feat[k] * ign_w[k*64 + t];
    g_nbt1[e*64 + t] = o;
}

// ---------------- 14. coord weights + segment scatter ----------------
__global__ void k_coord(const int* __restrict__ edges,
                        const float* __restrict__ cw1, const float* __restrict__ cb1,
                        const float* __restrict__ cw2)
{
    __shared__ float nb[64];
    __shared__ float red[128];
    int e = blockIdx.x, t = threadIdx.x;   // 128
    if (t < 64) nb[t] = g_nbt1[e*64 + t];
    __syncthreads();
    float acc = cb1[t];
#pragma unroll 8
    for (int k = 0; k < 64; k++) acc += nb[k] * cw1[k*128 + t];
    red[t] = siluf(acc) * cw2[t];
    __syncthreads();
    for (int st = 64; st > 0; st >>= 1) {
        if (t < st) red[t] += red[t + st];
        __syncthreads();
    }
    float w = red[0];
    int r = edges[e];
    if (t < 3)  atomicAdd(&g_segx[r*3 + t], g_cdiff[e*3 + t] * w);
    if (t == 3) atomicAdd(&g_cnt[r], 1.f);
    if (t >= 64) atomicAdd(&g_nbt0[r*64 + (t - 64)], nb[t - 64]);
}

// ---------------- 15. node update + coord finalize ----------------
__global__ void k_node(const float* __restrict__ h, const float* __restrict__ x,
                       const float* __restrict__ nw1, const float* __restrict__ nb1,
                       const float* __restrict__ nw2, const float* __restrict__ nb2,
                       float* __restrict__ out)
{
    __shared__ float a[64];
    __shared__ float hid[128];
    int n = blockIdx.x, t = threadIdx.x;   // 128
    if (t < 64) a[t] = g_nbt0[n*64 + t];
    __syncthreads();
    float acc = nb1[t];
#pragma unroll 8
    for (int k = 0; k < 64; k++) acc += a[k] * nw1[k*128 + t];
    hid[t] = siluf(acc);
    __syncthreads();
    if (t < 64) {
        float o = nb2[t];
#pragma unroll 8
        for (int k = 0; k < 128; k++) o += hid[k] * nw2[k*64 + t];
        out[n*64 + t] = h[n*64 + t] + o;
    } else if (t < 67) {
        int d = t - 64;
        float c = g_cnt[n];
        if (c < 1.f) c = 1.f;
        out[NN*64 + n*3 + d] = x[n*3 + d] + g_segx[n*3 + d] / c;
    }
}

__global__ void k_copy_ea(const float* __restrict__ ea, float* __restrict__ out)
{
    int i = blockIdx.x * blockDim.x + threadIdx.x;
    if (i < EE*4) out[NN*64 + NN*3 + i] = ea[i];
}

// ---------------- host ----------------
extern "C" void kernel_launch(void* const* d_in, const int* in_sizes, int n_in,
                              void* d_out, int out_size)
{
    const float* h     = (const float*)d_in[0];
    const float* x     = (const float*)d_in[1];
    const int*   edges = (const int*)d_in[2];
    const int*   nbe   = (const int*)d_in[3];
    const float* ea    = (const float*)d_in[4];
    int wb = n_in - 25;
    const float* ew1  = (const float*)d_in[wb + 0];
    const float* eb1  = (const float*)d_in[wb + 1];
    const float* ew2  = (const float*)d_in[wb + 2];
    const float* eb2  = (const float*)d_in[wb + 3];
    const float* p1w1 = (const float*)d_in[wb + 4];
    const float* p1b1 = (const float*)d_in[wb + 5];
    const float* p1w2 = (const float*)d_in[wb + 6];
    const float* p1b2 = (const float*)d_in[wb + 7];
    const float* p2w1 = (const float*)d_in[wb + 8];
    const float* p2b1 = (const float*)d_in[wb + 9];
    const float* p2w2 = (const float*)d_in[wb + 10];
    const float* p2b2 = (const float*)d_in[wb + 11];
    const float* p3w1 = (const float*)d_in[wb + 12];
    const float* p3b1 = (const float*)d_in[wb + 13];
    const float* p3w2 = (const float*)d_in[wb + 14];
    const float* p3b2 = (const float*)d_in[wb + 15];
    const float* ignw = (const float*)d_in[wb + 16];
    const float* ignb = (const float*)d_in[wb + 17];
    const float* cw1  = (const float*)d_in[wb + 18];
    const float* cb1  = (const float*)d_in[wb + 19];
    const float* cw2  = (const float*)d_in[wb + 20];
    const float* ndw1 = (const float*)d_in[wb + 21];
    const float* ndb1 = (const float*)d_in[wb + 22];
    const float* ndw2 = (const float*)d_in[wb + 23];
    const float* ndb2 = (const float*)d_in[wb + 24];
    float* out = (float*)d_out;

    cudaFuncSetAttribute(k_smlp,  cudaFuncAttributeMaxDynamicSharedMemorySize, (64*96 + 8192 + 8192) * 4);
    cudaFuncSetAttribute(k_zgemm, cudaFuncAttributeMaxDynamicSharedMemorySize, (64*68 + 64*128) * 4);

    void* p;
    cudaGetSymbolAddress(&p, g_map);   cudaMemsetAsync(p, 0, sizeof(int)*RTOT, 0);
    cudaGetSymbolAddress(&p, g_nnz);   cudaMemsetAsync(p, 0, sizeof(int), 0);
    cudaGetSymbolAddress(&p, g_Tval);  cudaMemsetAsync(p, 0, sizeof(float)*(size_t)SMAX*96, 0);
    cudaGetSymbolAddress(&p, g_SS);    cudaMemsetAsync(p, 0, sizeof(float)*(size_t)RTOT*64, 0);
    cudaGetSymbolAddress(&p, g_rowS1); cudaMemsetAsync(p, 0, sizeof(float)*EE*64, 0);
    cudaGetSymbolAddress(&p, g_colS2); cudaMemsetAsync(p, 0, sizeof(float)*EE*64, 0);
    cudaGetSymbolAddress(&p, g_cntA);  cudaMemsetAsync(p, 0, sizeof(int)*EE, 0);
    cudaGetSymbolAddress(&p, g_cntB);  cudaMemsetAsync(p, 0, sizeof(int)*EE, 0);
    cudaGetSymbolAddress(&p, g_segx);  cudaMemsetAsync(p, 0, sizeof(float)*NN*3, 0);
    cudaGetSymbolAddress(&p, g_cnt);   cudaMemsetAsync(p, 0, sizeof(float)*NN, 0);
    cudaGetSymbolAddress(&p, g_nbt0);  cudaMemsetAsync(p, 0, sizeof(float)*NN*FINW, 0);

    k_edge<<<EE, 128>>>(h, x, edges, ew1, eb1, ew2, eb2);
    k_flag<<<MM/256, 256>>>(nbe);
    k_compact<<<RTOT/256, 256>>>();
    k_scat<<<MM, 128>>>(nbe);
    k_const<<<1, 128>>>(p1b1, p1w2, p1b2, p2b1, p2w2, p2b2, p3w1, p3b1);
    k_smlp<<<SMAX/64, 256, (64*96 + 8192 + 8192) * 4>>>(p1w1, p1b1, p1w2, p1b2,
                                                        p2w1, p2b1, p2w2, p2b2);
    k_ab<<<1024, 128>>>(p3w1);
    k_cnt<<<SMAX/256, 256>>>();
    k_scan<<<1, 512>>>();
    k_fill<<<SMAX/256, 256>>>();
    k_ss<<<EE, 256>>>();
    k_zgemm<<<RTOT/64, 256, (64*68 + 64*128) * 4>>>(p3w1);
    k_tc<<<SMAX, 128>>>(p3w1);
    k_hrow<<<EE, 128>>>();
    k_hcol<<<EE, 128>>>();
    k_ign<<<513, 128>>>(p3w2, p3b2);
    k_nbt1<<<EE, 64>>>(ignw, ignb);
    k_coord<<<EE, 128>>>(edges, cw1, cb1, cw2);
    k_node<<<NN, 128>>>(h, x, ndw1, ndb1, ndw2, ndb2, out);
    k_copy_ea<<<8, 256>>>(ea, out);
}

// round 4
// speedup vs baseline: 3.9009x; 1.2816x over previous
#include <cuda_runtime.h>
#include <math.h>

#define NN 512
#define EE 512
#define MM 16384
#define FINW 64
#define RTOT (EE*EE)   // 262144
#define SMAX 16384

// ---------------- scratch (device globals) ----------------
__device__ float g_efn[EE*FINW];
__device__ float g_cdiff[EE*3];
__device__ int   g_map[RTOT];          // 0 = empty, else slot+1
__device__ int   g_cells[SMAX];
__device__ int   g_nnz;
__device__ float g_Tval[(size_t)SMAX*96];
__device__ float g_S1[(size_t)SMAX*64];
__device__ float g_S2[(size_t)SMAX*64];
__device__ float g_rowS1[EE*64];
__device__ float g_colS2[EE*64];
__device__ float g_c1[64], g_c2[64], g_u0[128];
__device__ float g_atab[EE*128], g_btab[EE*128];
__device__ int   g_cntA[EE], g_cntB[EE], g_offA[EE], g_offB[EE], g_curA[EE], g_curB[EE];
__device__ int   g_listA[SMAX], g_listB[SMAX];
__device__ float g_SS[(size_t)RTOT*64];     // 64 MB
__device__ float g_Ztc[(size_t)SMAX*128];   // 8 MB: W1t^T Tval per occupied slot
__device__ float g_Hrow[EE*128], g_Hcol[EE*128], g_Hdiag[EE*128];
__device__ float g_diag[EE*FINW], g_row[EE*FINW], g_col[EE*FINW];
__device__ float g_tot[FINW], g_tr[FINW];
__device__ float g_nbt1[EE*FINW];
__device__ float g_segx[NN*3];
__device__ float g_cnt[NN];
__device__ float g_nbt0[NN*FINW];

__device__ __forceinline__ float siluf(float v) {
    return v * __fdividef(1.f, 1.f + __expf(-v));
}

// ---------------- 1. edge encoder + coord_diff ----------------
__global__ void k_edge(const float* __restrict__ h, const float* __restrict__ x,
                       const int* __restrict__ edges,
                       const float* __restrict__ ew1, const float* __restrict__ eb1,
                       const float* __restrict__ ew2, const float* __restrict__ eb2)
{
    __shared__ float hcat[128];
    __shared__ float hid[128];
    int e = blockIdx.x, t = threadIdx.x;
    int r = edges[e], c = edges[EE + e];
    if (t < 64) hcat[t] = h[r*64 + t];
    else        hcat[t] = h[c*64 + (t - 64)];
    if (t < 3)  g_cdiff[e*3 + t] = x[r*3 + t] - x[c*3 + t];
    __syncthreads();
    float acc = eb1[t];
#pragma unroll 8
    for (int k = 0; k < 128; k++) acc += hcat[k] * ew1[k*128 + t];
    hid[t] = siluf(acc);
    __syncthreads();
    if (t < 64) {
        float o = eb2[t];
#pragma unroll 8
        for (int k = 0; k < 128; k++) o += hid[k] * ew2[k*64 + t];
        g_efn[e*64 + t] = o;
    }
}

// ---------------- 2. occupancy flag + compaction ----------------
__global__ void k_flag(const int* __restrict__ nbe)
{
    int m = blockIdx.x * blockDim.x + threadIdx.x;
    if (m < MM) g_map[nbe[m]*EE + nbe[MM + m]] = 1;
}

__global__ void k_compact()
{
    int cell = blockIdx.x * blockDim.x + threadIdx.x;
    if (cell < RTOT && g_map[cell] != 0) {
        int slot = atomicAdd(&g_nnz, 1);
        g_map[cell] = slot + 1;
        g_cells[slot] = cell;
    }
}

// ---------------- 3. VTV + PE + scatter into compact T ----------------
__global__ void k_scat(const int* __restrict__ nbe)
{
    int m = blockIdx.x, f = threadIdx.x;  // 128 threads, 96 active
    if (f >= 96) return;
    int a = nbe[m], b = nbe[MM + m];
    float val;
    if (f < 32) {
        float vtv = 0.f;
#pragma unroll
        for (int d = 0; d < 3; d++) vtv += g_cdiff[a*3 + d] * g_cdiff[b*3 + d];
        int i = f >> 1;
        float ang = vtv * 16.f * expf(-0.5756462732485115f * (float)i);
        val = (f & 1) ? cosf(ang) : sinf(ang);
    } else {
        val = g_efn[a*64 + (f - 32)] * g_efn[b*64 + (f - 32)];
    }
    int slot = g_map[a*EE + b] - 1;
    atomicAdd(&g_Tval[(size_t)slot*96 + f], val);
}

// ---------------- 4. constants c1,c2,u0 ----------------
__global__ void k_const(const float* __restrict__ p1b1, const float* __restrict__ p1w2, const float* __restrict__ p1b2,
                        const float* __restrict__ p2b1, const float* __restrict__ p2w2, const float* __restrict__ p2b2,
                        const float* __restrict__ p3w1, const float* __restrict__ p3b1)
{
    __shared__ float h1[128], h2[128], cc[64];
    int t = threadIdx.x;  // 128
    h1[t] = siluf(p1b1[t]);
    h2[t] = siluf(p2b1[t]);
    __syncthreads();
    if (t < 64) {
        float a = p1b2[t], b = p2b2[t];
#pragma unroll 8
        for (int k = 0; k < 128; k++) { a += h1[k]*p1w2[k*64+t]; b += h2[k]*p2w2[k*64+t]; }
        g_c1[t] = a; g_c2[t] = b; cc[t] = a*b;
    }
    __syncthreads();
    float u = p3b1[t];
#pragma unroll 8
    for (int f = 0; f < 64; f++) u += 512.f * cc[f] * p3w1[(96+f)*128 + t];
    g_u0[t] = u;
}

// ---------------- fused 2-layer MLP on 64-row tile (K1 -> 128 -> 64) ----------------
template<int K1>
__device__ __forceinline__ void mlp_tile(const float* sA, float* sBuf, float* sHid,
    const float* __restrict__ W1, const float* __restrict__ b1,
    const float* __restrict__ W2, const float* __restrict__ b2,
    float acc2[4][4])
{
    int tid = threadIdx.x, ty = tid >> 4, tx = tid & 15;
    float acc[4][8];
#pragma unroll
    for (int i = 0; i < 4; i++)
#pragma unroll
        for (int u = 0; u < 8; u++) acc[i][u] = 0.f;

    for (int kc = 0; kc < K1; kc += 32) {
        for (int i = tid; i < 32*128; i += 256) sBuf[i] = W1[kc*128 + i];
        __syncthreads();
#pragma unroll
        for (int k = 0; k < 32; k++) {
            float a[4];
#pragma unroll
            for (int i = 0; i < 4; i++) a[i] = sA[(ty*4 + i)*K1 + kc + k];
            float4 b0 = *(const float4*)&sBuf[k*128 + tx*8];
            float4 b1v = *(const float4*)&sBuf[k*128 + tx*8 + 4];
#pragma unroll
            for (int i = 0; i < 4; i++) {
                float av = a[i];
                acc[i][0] += av * b0.x;  acc[i][1] += av * b0.y;
                acc[i][2] += av * b0.z;  acc[i][3] += av * b0.w;
                acc[i][4] += av * b1v.x; acc[i][5] += av * b1v.y;
                acc[i][6] += av * b1v.z; acc[i][7] += av * b1v.w;
            }
        }
        __syncthreads();
    }
#pragma unroll
    for (int i = 0; i < 4; i++)
#pragma unroll
        for (int u = 0; u < 8; u++) {
            int j = tx*8 + u;
            sHid[(ty*4 + i)*128 + j] = siluf(acc[i][u] + b1[j]);
        }
    for (int i = tid; i < 128*64; i += 256) sBuf[i] = W2[i];
    __syncthreads();
#pragma unroll
    for (int i = 0; i < 4; i++)
#pragma unroll
        for (int u = 0; u < 4; u++) acc2[i][u] = 0.f;
#pragma unroll 4
    for (int k = 0; k < 128; k++) {
        float a[4];
#pragma unroll
        for (int i = 0; i < 4; i++) a[i] = sHid[(ty*4 + i)*128 + k];
        float4 b = *(const float4*)&sBuf[k*64 + tx*4];
#pragma unroll
        for (int i = 0; i < 4; i++) {
            float av = a[i];
            acc2[i][0] += av * b.x; acc2[i][1] += av * b.y;
            acc2[i][2] += av * b.z; acc2[i][3] += av * b.w;
        }
    }
#pragma unroll
    for (int i = 0; i < 4; i++)
#pragma unroll
        for (int u = 0; u < 4; u++) acc2[i][u] += b2[tx*4 + u];
    __syncthreads();
}

// ---------------- 5. sparse MLPs: S1,S2 + row/col sums ----------------
__global__ void __launch_bounds__(256) k_smlp(
    const float* __restrict__ p1w1, const float* __restrict__ p1b1,
    const float* __restrict__ p1w2, const float* __restrict__ p1b2,
    const float* __restrict__ p2w1, const float* __restrict__ p2b1,
    const float* __restrict__ p2w2, const float* __restrict__ p2b2)
{
    extern __shared__ float smem[];
    float* sA   = smem;            // 64*96
    float* sBuf = sA + 64*96;
    float* sHid = sBuf + 8192;
    int base = blockIdx.x * 64;
    int tid = threadIdx.x, ty = tid >> 4, tx = tid & 15;
    int nnz = g_nnz;

    const float* Tp = &g_Tval[(size_t)base * 96];
    for (int i = tid; i < 64*96; i += 256) sA[i] = Tp[i];
    __syncthreads();

    float acc2[4][4];
    mlp_tile<96>(sA, sBuf, sHid, p1w1, p1b1, p1w2, p1b2, acc2);
#pragma unroll
    for (int i = 0; i < 4; i++) {
        int slot = base + ty*4 + i;
        if (slot < nnz) {
            int cell = g_cells[slot];
#pragma unroll
            for (int u = 0; u < 4; u++) {
                int f = tx*4 + u;
                float v = acc2[i][u] - g_c1[f];
                g_S1[(size_t)slot*64 + f] = v;
                atomicAdd(&g_rowS1[(cell >> 9)*64 + f], v);
            }
        }
    }

    mlp_tile<96>(sA, sBuf, sHid, p2w1, p2b1, p2w2, p2b2, acc2);
#pragma unroll
    for (int i = 0; i < 4; i++) {
        int slot = base + ty*4 + i;
        if (slot < nnz) {
            int cell = g_cells[slot];
#pragma unroll
            for (int u = 0; u < 4; u++) {
                int f = tx*4 + u;
                float v = acc2[i][u] - g_c2[f];
                g_S2[(size_t)slot*64 + f] = v;
                atomicAdd(&g_colS2[(cell & 511)*64 + f], v);
            }
        }
    }
}

// ---------------- 6. a_i / b_j tables ----------------
__global__ void k_ab(const float* __restrict__ p3w1)
{
    __shared__ float r[64];
    int b = blockIdx.x, t = threadIdx.x;  // 128
    if (b < 512) {
        int i = b;
        if (t < 64) r[t] = g_rowS1[i*64 + t] * g_c2[t];
        __syncthreads();
        float a = 0.f;
#pragma unroll 8
        for (int f = 0; f < 64; f++) a += r[f] * p3w1[(96+f)*128 + t];
        g_atab[i*128 + t] = a;
    } else {
        int j = b - 512;
        if (t < 64) r[t] = g_colS2[j*64 + t] * g_c1[t];
        __syncthreads();
        float a = 0.f;
#pragma unroll 8
        for (int f = 0; f < 64; f++) a += r[f] * p3w1[(96+f)*128 + t];
        g_btab[j*128 + t] = a;
    }
}

// ---------------- 7. group slots by middle index ----------------
__global__ void k_cnt()
{
    int s = blockIdx.x * blockDim.x + threadIdx.x;
    if (s < g_nnz) {
        int cell = g_cells[s];
        atomicAdd(&g_cntA[cell & 511], 1);   // S1 entries grouped by k = col
        atomicAdd(&g_cntB[cell >> 9], 1);    // S2 entries grouped by k = row
    }
}

__global__ void k_scan()
{
    __shared__ int s[512];
    int t = threadIdx.x;  // 512
    s[t] = g_cntA[t]; __syncthreads();
    for (int d = 1; d < 512; d <<= 1) {
        int v = (t >= d) ? s[t - d] : 0;
        __syncthreads();
        s[t] += v;
        __syncthreads();
    }
    int exc = s[t] - g_cntA[t];
    g_offA[t] = exc; g_curA[t] = exc;
    __syncthreads();
    s[t] = g_cntB[t]; __syncthreads();
    for (int d = 1; d < 512; d <<= 1) {
        int v = (t >= d) ? s[t - d] : 0;
        __syncthreads();
        s[t] += v;
        __syncthreads();
    }
    exc = s[t] - g_cntB[t];
    g_offB[t] = exc; g_curB[t] = exc;
}

__global__ void k_fill()
{
    int s = blockIdx.x * blockDim.x + threadIdx.x;
    if (s < g_nnz) {
        int cell = g_cells[s];
        int pa = atomicAdd(&g_curA[cell & 511], 1);
        g_listA[pa] = s;
        int pb = atomicAdd(&g_curB[cell >> 9], 1);
        g_listB[pb] = s;
    }
}

// ---------------- 8. sparse-sparse product: SS[i,j,f] += S1[i,k,f]*S2[k,j,f] ----------------
__global__ void __launch_bounds__(256) k_ss()
{
    __shared__ float sA[64*64];
    __shared__ float sB[64*64];
    __shared__ int ri[64], cj[64];
    int k = blockIdx.x, tid = threadIdx.x;
    int cA = g_cntA[k], cB = g_cntB[k];
    if (cA == 0 || cB == 0) return;
    int oA = g_offA[k], oB = g_offB[k];

    for (int a0 = 0; a0 < cA; a0 += 64) {
        int nA = min(64, cA - a0);
        __syncthreads();
        for (int x = tid; x < nA*64; x += 256) {
            int r = x >> 6;
            int slot = g_listA[oA + a0 + r];
            sA[x] = g_S1[(size_t)slot*64 + (x & 63)];
        }
        for (int r = tid; r < nA; r += 256) ri[r] = g_cells[g_listA[oA + a0 + r]] >> 9;
        for (int b0 = 0; b0 < cB; b0 += 64) {
            int nB = min(64, cB - b0);
            __syncthreads();
            for (int x = tid; x < nB*64; x += 256) {
                int c = x >> 6;
                int slot = g_listB[oB + b0 + c];
                sB[x] = g_S2[(size_t)slot*64 + (x & 63)];
            }
            for (int c = tid; c < nB; c += 256) cj[c] = g_cells[g_listB[oB + b0 + c]] & 511;
            __syncthreads();
            int f = tid & 63, pc = tid >> 6;
            for (int r = 0; r < nA; r++) {
                float av = sA[r*64 + f];
                int ibase = ri[r];
                for (int c = pc; c < nB; c += 4) {
                    atomicAdd(&g_SS[((size_t)ibase*512 + cj[c])*64 + f], av * sB[c*64 + f]);
                }
            }
        }
    }
}

// ---------------- 9. Ztc[slot] = W1t^T Tval[slot] ----------------
__global__ void k_tc(const float* __restrict__ p3w1)
{
    __shared__ float tv[96];
    int slot = blockIdx.x, t = threadIdx.x;  // 128
    if (slot >= g_nnz) return;
    if (t < 96) tv[t] = g_Tval[(size_t)slot*96 + t];
    __syncthreads();
    float acc = 0.f;
#pragma unroll 8
    for (int k = 0; k < 96; k++) acc += tv[k] * p3w1[k*128 + t];
    g_Ztc[(size_t)slot*128 + t] = acc;
}

// ---------------- 10. FUSED: Z-GEMM + additive terms + SiLU + row/col/diag reductions ----------------
__global__ void __launch_bounds__(256) k_fused(const float* __restrict__ p3w1)
{
    extern __shared__ float dsm[];
    float* sA   = dsm;                  // [64][68]
    float* sB   = sA + 64*68;           // [64][128]  W1m
    float* srow = sB + 8192;            // [128]
    int*  sslot = (int*)(srow + 128);   // [64]

    size_t base = (size_t)blockIdx.x * 64;
    int i_glob = (int)(base >> 9);
    int j0 = (int)(base & 511);
    int tid = threadIdx.x;

    for (int x = tid*4; x < 4096; x += 1024) {
        float4 v = *(const float4*)&g_SS[base*64 + x];
        int cell = x >> 6, k = x & 63;
        *(float4*)&sA[cell*68 + k] = v;
    }
    for (int x = tid*4; x < 8192; x += 1024)
        *(float4*)&sB[x] = *(const float4*)&p3w1[96*128 + x];
    if (tid < 128) srow[tid] = 0.f;
    if (tid < 64)  sslot[tid] = g_map[base + tid] - 1;
    __syncthreads();

    int ty = tid >> 4, tx = tid & 15;
    float acc[4][8];
#pragma unroll
    for (int i = 0; i < 4; i++)
#pragma unroll
        for (int u = 0; u < 8; u++) acc[i][u] = 0.f;

#pragma unroll 16
    for (int k = 0; k < 64; k++) {
        float a[4];
#pragma unroll
        for (int i = 0; i < 4; i++) a[i] = sA[(ty*4 + i)*68 + k];
        float4 b0 = *(const float4*)&sB[k*128 + tx*8];
        float4 b1 = *(const float4*)&sB[k*128 + tx*8 + 4];
#pragma unroll
        for (int i = 0; i < 4; i++) {
            float av = a[i];
            acc[i][0] += av * b0.x; acc[i][1] += av * b0.y;
            acc[i][2] += av * b0.z; acc[i][3] += av * b0.w;
            acc[i][4] += av * b1.x; acc[i][5] += av * b1.y;
            acc[i][6] += av * b1.z; acc[i][7] += av * b1.w;
        }
    }

    // additive per-column terms: u0 + atab[i]
    float add[8];
    {
        float4 u0a = *(const float4*)&g_u0[tx*8];
        float4 u0b = *(const float4*)&g_u0[tx*8 + 4];
        float4 aa  = *(const float4*)&g_atab[i_glob*128 + tx*8];
        float4 ab  = *(const float4*)&g_atab[i_glob*128 + tx*8 + 4];
        add[0]=u0a.x+aa.x; add[1]=u0a.y+aa.y; add[2]=u0a.z+aa.z; add[3]=u0a.w+aa.w;
        add[4]=u0b.x+ab.x; add[5]=u0b.y+ab.y; add[6]=u0b.z+ab.z; add[7]=u0b.w+ab.w;
    }

    float rsum[8];
#pragma unroll
    for (int u = 0; u < 8; u++) rsum[u] = 0.f;

#pragma unroll
    for (int i = 0; i < 4; i++) {
        int r = ty*4 + i;
        int j = j0 + r;
        float4 b0 = *(const float4*)&g_btab[j*128 + tx*8];
        float4 b1 = *(const float4*)&g_btab[j*128 + tx*8 + 4];
        float zb[8] = {b0.x, b0.y, b0.z, b0.w, b1.x, b1.y, b1.z, b1.w};
        int slot = sslot[r];
        if (slot >= 0) {
            float4 t0 = *(const float4*)&g_Ztc[(size_t)slot*128 + tx*8];
            float4 t1 = *(const float4*)&g_Ztc[(size_t)slot*128 + tx*8 + 4];
            zb[0]+=t0.x; zb[1]+=t0.y; zb[2]+=t0.z; zb[3]+=t0.w;
            zb[4]+=t1.x; zb[5]+=t1.y; zb[6]+=t1.z; zb[7]+=t1.w;
        }
        bool isdiag = (j == i_glob);
#pragma unroll
        for (int u = 0; u < 8; u++) {
            float hv = siluf(acc[i][u] + add[u] + zb[u]);
            rsum[u] += hv;
            atomicAdd(&g_Hcol[j*128 + tx*8 + u], hv);
            if (isdiag) g_Hdiag[i_glob*128 + tx*8 + u] = hv;
        }
    }
#pragma unroll
    for (int u = 0; u < 8; u++) atomicAdd(&srow[tx*8 + u], rsum[u]);
    __syncthreads();
    if (tid < 128) atomicAdd(&g_Hrow[i_glob*128 + tid], srow[tid]);
}

// ---------------- 11. apply W2 to aggregates ----------------
__global__ void k_ign(const float* __restrict__ w2, const float* __restrict__ b2)
{
    __shared__ float hd[128], hr[128], hc[128];
    int e = blockIdx.x, t = threadIdx.x;  // 128 threads, 513 blocks
    if (e < 512) {
        hd[t] = g_Hdiag[e*128 + t];
        hr[t] = g_Hrow[e*128 + t];
        hc[t] = g_Hcol[e*128 + t];
        __syncthreads();
        if (t < 64) {
            float d = 0.f, r = 0.f, c = 0.f;
#pragma unroll 8
            for (int k = 0; k < 128; k++) {
                float w = w2[k*64 + t];
                d += hd[k]*w; r += hr[k]*w; c += hc[k]*w;
            }
            float bb = b2[t];
            g_diag[e*64 + t] = d + bb;
            g_row[e*64 + t]  = r + 512.f*bb;
            g_col[e*64 + t]  = c + 512.f*bb;
        }
    } else {
        float st = 0.f, sr = 0.f;
        for (int i = 0; i < 512; i++) { st += g_Hrow[i*128 + t]; sr += g_Hdiag[i*128 + t]; }
        hd[t] = st; hr[t] = sr;
        __syncthreads();
        if (t < 64) {
            float a = 0.f, b = 0.f;
#pragma unroll 8
            for (int k = 0; k < 128; k++) { float w = w2[k*64 + t]; a += hd[k]*w; b += hr[k]*w; }
            g_tot[t] = a + 262144.f*b2[t];
            g_tr[t]  = b + 512.f*b2[t];
        }
    }
}

// ---------------- 12. IGN linear ----------------
__global__ void k_nbt1(const float* __restrict__ ign_w, const float* __restrict__ ign_b)
{
    __shared__ float feat[320];
    int e = blockIdx.x, t = threadIdx.x;   // 64
    feat[t]       = g_diag[e*64 + t];
    feat[64 + t]  = g_row[e*64 + t];
    feat[128 + t] = g_col[e*64 + t];
    feat[192 + t] = g_tot[t];
    feat[256 + t] = g_tr[t];
    __syncthreads();
    float o = ign_b[t];
#pragma unroll 8
    for (int k = 0; k < 320; k++) o += feat[k] * ign_w[k*64 + t];
    g_nbt1[e*64 + t] = o;
}

// ---------------- 13. coord weights + segment scatter ----------------
__global__ void k_coord(const int* __restrict__ edges,
                        const float* __restrict__ cw1, const float* __restrict__ cb1,
                        const float* __restrict__ cw2)
{
    __shared__ float nb[64];
    __shared__ float red[128];
    int e = blockIdx.x, t = threadIdx.x;   // 128
    if (t < 64) nb[t] = g_nbt1[e*64 + t];
    __syncthreads();
    float acc = cb1[t];
#pragma unroll 8
    for (int k = 0; k < 64; k++) acc += nb[k] * cw1[k*128 + t];
    red[t] = siluf(acc) * cw2[t];
    __syncthreads();
    for (int st = 64; st > 0; st >>= 1) {
        if (t < st) red[t] += red[t + st];
        __syncthreads();
    }
    float w = red[0];
    int r = edges[e];
    if (t < 3)  atomicAdd(&g_segx[r*3 + t], g_cdiff[e*3 + t] * w);
    if (t == 3) atomicAdd(&g_cnt[r], 1.f);
    if (t >= 64) atomicAdd(&g_nbt0[r*64 + (t - 64)], nb[t - 64]);
}

// ---------------- 14. node update + coord finalize ----------------
__global__ void k_node(const float* __restrict__ h, const float* __restrict__ x,
                       const float* __restrict__ nw1, const float* __restrict__ nb1,
                       const float* __restrict__ nw2, const float* __restrict__ nb2,
                       float* __restrict__ out)
{
    __shared__ float a[64];
    __shared__ float hid[128];
    int n = blockIdx.x, t = threadIdx.x;   // 128
    if (t < 64) a[t] = g_nbt0[n*64 + t];
    __syncthreads();
    float acc = nb1[t];
#pragma unroll 8
    for (int k = 0; k < 64; k++) acc += a[k] * nw1[k*128 + t];
    hid[t] = siluf(acc);
    __syncthreads();
    if (t < 64) {
        float o = nb2[t];
#pragma unroll 8
        for (int k = 0; k < 128; k++) o += hid[k] * nw2[k*64 + t];
        out[n*64 + t] = h[n*64 + t] + o;
    } else if (t < 67) {
        int d = t - 64;
        float c = g_cnt[n];
        if (c < 1.f) c = 1.f;
        out[NN*64 + n*3 + d] = x[n*3 + d] + g_segx[n*3 + d] / c;
    }
}

__global__ void k_copy_ea(const float* __restrict__ ea, float* __restrict__ out)
{
    int i = blockIdx.x * blockDim.x + threadIdx.x;
    if (i < EE*4) out[NN*64 + NN*3 + i] = ea[i];
}

// ---------------- host ----------------
extern "C" void kernel_launch(void* const* d_in, const int* in_sizes, int n_in,
                              void* d_out, int out_size)
{
    const float* h     = (const float*)d_in[0];
    const float* x     = (const float*)d_in[1];
    const int*   edges = (const int*)d_in[2];
    const int*   nbe   = (const int*)d_in[3];
    const float* ea    = (const float*)d_in[4];
    int wb = n_in - 25;
    const float* ew1  = (const float*)d_in[wb + 0];
    const float* eb1  = (const float*)d_in[wb + 1];
    const float* ew2  = (const float*)d_in[wb + 2];
    const float* eb2  = (const float*)d_in[wb + 3];
    const float* p1w1 = (const float*)d_in[wb + 4];
    const float* p1b1 = (const float*)d_in[wb + 5];
    const float* p1w2 = (const float*)d_in[wb + 6];
    const float* p1b2 = (const float*)d_in[wb + 7];
    const float* p2w1 = (const float*)d_in[wb + 8];
    const float* p2b1 = (const float*)d_in[wb + 9];
    const float* p2w2 = (const float*)d_in[wb + 10];
    const float* p2b2 = (const float*)d_in[wb + 11];
    const float* p3w1 = (const float*)d_in[wb + 12];
    const float* p3b1 = (const float*)d_in[wb + 13];
    const float* p3w2 = (const float*)d_in[wb + 14];
    const float* p3b2 = (const float*)d_in[wb + 15];
    const float* ignw = (const float*)d_in[wb + 16];
    const float* ignb = (const float*)d_in[wb + 17];
    const float* cw1  = (const float*)d_in[wb + 18];
    const float* cb1  = (const float*)d_in[wb + 19];
    const float* cw2  = (const float*)d_in[wb + 20];
    const float* ndw1 = (const float*)d_in[wb + 21];
    const float* ndb1 = (const float*)d_in[wb + 22];
    const float* ndw2 = (const float*)d_in[wb + 23];
    const float* ndb2 = (const float*)d_in[wb + 24];
    float* out = (float*)d_out;

    int smlp_smem  = (64*96 + 8192 + 8192) * 4;
    int fused_smem = (64*68 + 8192 + 128 + 64) * 4;
    cudaFuncSetAttribute(k_smlp,  cudaFuncAttributeMaxDynamicSharedMemorySize, smlp_smem);
    cudaFuncSetAttribute(k_fused, cudaFuncAttributeMaxDynamicSharedMemorySize, fused_smem);

    void* p;
    cudaGetSymbolAddress(&p, g_map);   cudaMemsetAsync(p, 0, sizeof(int)*RTOT, 0);
    cudaGetSymbolAddress(&p, g_nnz);   cudaMemsetAsync(p, 0, sizeof(int), 0);
    cudaGetSymbolAddress(&p, g_Tval);  cudaMemsetAsync(p, 0, sizeof(float)*(size_t)SMAX*96, 0);
    cudaGetSymbolAddress(&p, g_SS);    cudaMemsetAsync(p, 0, sizeof(float)*(size_t)RTOT*64, 0);
    cudaGetSymbolAddress(&p, g_rowS1); cudaMemsetAsync(p, 0, sizeof(float)*EE*64, 0);
    cudaGetSymbolAddress(&p, g_colS2); cudaMemsetAsync(p, 0, sizeof(float)*EE*64, 0);
    cudaGetSymbolAddress(&p, g_cntA);  cudaMemsetAsync(p, 0, sizeof(int)*EE, 0);
    cudaGetSymbolAddress(&p, g_cntB);  cudaMemsetAsync(p, 0, sizeof(int)*EE, 0);
    cudaGetSymbolAddress(&p, g_Hrow);  cudaMemsetAsync(p, 0, sizeof(float)*EE*128, 0);
    cudaGetSymbolAddress(&p, g_Hcol);  cudaMemsetAsync(p, 0, sizeof(float)*EE*128, 0);
    cudaGetSymbolAddress(&p, g_segx);  cudaMemsetAsync(p, 0, sizeof(float)*NN*3, 0);
    cudaGetSymbolAddress(&p, g_cnt);   cudaMemsetAsync(p, 0, sizeof(float)*NN, 0);
    cudaGetSymbolAddress(&p, g_nbt0);  cudaMemsetAsync(p, 0, sizeof(float)*NN*FINW, 0);

    k_edge<<<EE, 128>>>(h, x, edges, ew1, eb1, ew2, eb2);
    k_flag<<<MM/256, 256>>>(nbe);
    k_compact<<<RTOT/256, 256>>>();
    k_scat<<<MM, 128>>>(nbe);
    k_const<<<1, 128>>>(p1b1, p1w2, p1b2, p2b1, p2w2, p2b2, p3w1, p3b1);
    k_smlp<<<SMAX/64, 256, smlp_smem>>>(p1w1, p1b1, p1w2, p1b2,
                                        p2w1, p2b1, p2w2, p2b2);
    k_ab<<<1024, 128>>>(p3w1);
    k_tc<<<SMAX, 128>>>(p3w1);
    k_cnt<<<SMAX/256, 256>>>();
    k_scan<<<1, 512>>>();
    k_fill<<<SMAX/256, 256>>>();
    k_ss<<<EE, 256>>>();
    k_fused<<<RTOT/64, 256, fused_smem>>>(p3w1);
    k_ign<<<513, 128>>>(p3w2, p3b2);
    k_nbt1<<<EE, 64>>>(ignw, ignb);
    k_coord<<<EE, 128>>>(edges, cw1, cb1, cw2);
    k_node<<<NN, 128>>>(h, x, ndw1, ndb1, ndw2, ndb2, out);
    k_copy_ea<<<8, 256>>>(ea, out);
}